// round 11
// baseline (speedup 1.0000x reference)
#include <cuda_runtime.h>
#include <cuda_fp16.h>
#include <cstdint>

#define DINLINE __device__ __forceinline__

constexpr int T   = 2048;   // tokens
constexpr int H   = 2048;   // hidden
constexpr int NE  = 16;     // experts
constexpr int IE  = 512;    // expert intermediate
constexpr int ISZ = 2048;   // shared intermediate
constexpr int MAXROWS  = 6144;  // 4096 pairs + 16*128 tile padding
constexpr int MAXTILES = 48;

constexpr int BM = 128, BN = 128, BK = 16;
constexpr int PW = 10;        // padded stride in half2 words (8 data + 2 pad)
constexpr int THREADS = 512;  // 16 warps, warp tile 32x32

// ---------------- scratch (device globals; no allocation allowed) ------------
__device__ int   g_counts[NE];
__device__ int   g_off[NE];
__device__ int   g_cursor[NE];
__device__ int   g_tile_expert[MAXTILES];
__device__ int   g_rowtok[MAXROWS];
__device__ float g_roww[MAXROWS];
__device__ int   g_sel[T * 2];
__device__ float g_wk[T * 2];
__device__ int   g_pairslot[T * 2];
__device__ float g_gate[T];
__device__ float g_mid12[(size_t)MAXROWS * 1024];   // expert gate|up raw
__device__ float g_hmid [(size_t)MAXROWS * IE];     // expert swiglu * weight
__device__ float g_outp [(size_t)MAXROWS * H];      // expert partial outputs
__device__ float g_smid [(size_t)T * 2 * ISZ];      // shared gate|up raw
__device__ float g_shmid[(size_t)T * ISZ];          // shared swiglu

// ---------------- small kernels ---------------------------------------------
__global__ void zero_init() {
    int i = blockIdx.x * blockDim.x + threadIdx.x;
    if (i < MAXROWS) { g_rowtok[i] = -1; g_roww[i] = 0.f; }
    if (i < NE) g_counts[i] = 0;
}

// One warp per token: 16 router logits + 1 shared-gate logit.
__global__ void router_k(const float* __restrict__ X,
                         const float* __restrict__ GW,
                         const float* __restrict__ SGW) {
    __shared__ float Ws[17][128];
    int lane = threadIdx.x & 31, warp = threadIdx.x >> 5;
    int t = blockIdx.x * 4 + warp;

    float acc[17];
#pragma unroll
    for (int e = 0; e < 17; e++) acc[e] = 0.f;

    for (int k0 = 0; k0 < H; k0 += 128) {
        __syncthreads();
        for (int j = threadIdx.x; j < 17 * 128; j += 128) {
            int e = j >> 7, kk = j & 127;
            Ws[e][kk] = (e < 16) ? GW[e * H + k0 + kk] : SGW[k0 + kk];
        }
        __syncthreads();
        float xv[4];
#pragma unroll
        for (int i = 0; i < 4; i++) xv[i] = X[(size_t)t * H + k0 + i * 32 + lane];
#pragma unroll
        for (int e = 0; e < 17; e++) {
#pragma unroll
            for (int i = 0; i < 4; i++) acc[e] += xv[i] * Ws[e][i * 32 + lane];
        }
    }
#pragma unroll
    for (int e = 0; e < 17; e++) {
        float v = acc[e];
#pragma unroll
        for (int o = 16; o > 0; o >>= 1) v += __shfl_xor_sync(0xffffffffu, v, o);
        acc[e] = v;
    }
    if (lane == 0) {
        int i1 = 0;
        for (int e = 1; e < 16; e++) if (acc[e] > acc[i1]) i1 = e;
        int i2 = (i1 == 0) ? 1 : 0;
        for (int e = 0; e < 16; e++) if (e != i1 && acc[e] > acc[i2]) i2 = e;
        float m  = acc[i1];
        float e1 = expf(acc[i1] - m), e2 = expf(acc[i2] - m);
        float s  = e1 + e2;
        g_sel[t * 2] = i1;  g_sel[t * 2 + 1] = i2;
        g_wk [t * 2] = e1 / s;  g_wk [t * 2 + 1] = e2 / s;
        atomicAdd(&g_counts[i1], 1);
        atomicAdd(&g_counts[i2], 1);
        g_gate[t] = 1.f / (1.f + expf(-acc[16]));
    }
}

__global__ void offsets_k() {
    if (threadIdx.x == 0 && blockIdx.x == 0) {
        int off = 0, tile = 0;
        for (int e = 0; e < NE; e++) {
            g_off[e] = off;
            g_cursor[e] = 0;
            int nt = (g_counts[e] + BM - 1) / BM;
            for (int j = 0; j < nt; j++) g_tile_expert[tile++] = e;
            off += nt * BM;
        }
        for (; tile < MAXTILES; tile++) g_tile_expert[tile] = -1;
    }
}

__global__ void scatter_k() {
    int t = blockIdx.x * blockDim.x + threadIdx.x;
    if (t >= T) return;
#pragma unroll
    for (int k = 0; k < 2; k++) {
        int e   = g_sel[t * 2 + k];
        int pos = atomicAdd(&g_cursor[e], 1);
        int row = g_off[e] + pos;
        g_rowtok[row] = t;
        g_roww[row]   = g_wk[t * 2 + k];
        g_pairslot[t * 2 + k] = row;
    }
}

// ---------------- fp16 MMA GEMM ----------------------------------------------
DINLINE unsigned h2pack(float x, float y) {
    __half2 h = __floats2half2_rn(x, y);
    return *reinterpret_cast<unsigned*>(&h);
}
DINLINE void mma16(float* c, const unsigned* a, unsigned b0, unsigned b1) {
    asm volatile(
        "mma.sync.aligned.m16n8k16.row.col.f32.f16.f16.f32 "
        "{%0,%1,%2,%3}, {%4,%5,%6,%7}, {%8,%9}, {%0,%1,%2,%3};"
        : "+f"(c[0]), "+f"(c[1]), "+f"(c[2]), "+f"(c[3])
        : "r"(a[0]), "r"(a[1]), "r"(a[2]), "r"(a[3]), "r"(b0), "r"(b1));
}

// PAIR 0: blocks [0, 384)   -> expert gate/up, C[row,1024], K=2048
//         blocks [384, 896) -> shared gate/up, C[t,4096],   K=2048 (Wa1=ws_gate, Wb1=ws_up)
// PAIR 1: blocks [0, 768)   -> expert down,    C[row,2048], K=512
//         blocks [768,1024) -> shared down,    out,         K=2048 (Wa1=ws_down)
template <int PAIR>
__global__ void __launch_bounds__(THREADS, 1)
gemm_k(const float* __restrict__ X,
       const float* __restrict__ Wa0, const float* __restrict__ Wb0,
       const float* __restrict__ Wa1, const float* __restrict__ Wb1,
       float* __restrict__ Out) {
    __shared__ __align__(16) unsigned As[2][BM * PW];
    __shared__ __align__(16) unsigned Bs[2][BN * PW];

    const int bid = blockIdx.x;
    const int tid = threadIdx.x;

    bool first;
    int bx, by;
    int ksteps;
    if constexpr (PAIR == 0) {
        first = bid < 384;
        if (first) { bx = bid & 7;  by = bid >> 3; }
        else       { int r = bid - 384; bx = r & 31; by = r >> 5; }
        ksteps = 128;
    } else {
        first = bid < 768;
        if (first) { bx = bid & 15; by = bid >> 4; ksteps = 32; }
        else       { int r = bid - 768; bx = r & 15; by = r >> 4; ksteps = 128; }
    }

    int e = 0;
    if (first) {                       // expert modes need tile->expert
        e = g_tile_expert[by];
        if (e < 0) return;
    }
    const int m0 = by * BM, n0 = bx * BN;

    // ---- loader assignment: each thread loads ONE float4 of A and of B ----
    const int arow = tid >> 2;         // 0..127
    const int ac4  = tid & 3;          // float4 index in BK slab
    const int sdst = arow * PW + ac4 * 2;

    const float* aptr = nullptr;
    const float* bptr;
    if constexpr (PAIR == 0) {
        if (first) {
            int tok = g_rowtok[m0 + arow];
            if (tok >= 0) aptr = X + (size_t)tok * H + ac4 * 4;
            int n = n0 + arow;
            bptr = ((n < IE) ? (Wa0 + ((size_t)e * IE + n) * H)
                             : (Wb0 + ((size_t)e * IE + (n - IE)) * H)) + ac4 * 4;
        } else {
            aptr = X + (size_t)(m0 + arow) * H + ac4 * 4;
            int n = n0 + arow;
            bptr = ((n < ISZ) ? (Wa1 + (size_t)n * H)
                              : (Wb1 + (size_t)(n - ISZ) * H)) + ac4 * 4;
        }
    } else {
        if (first) {
            aptr = g_hmid + (size_t)(m0 + arow) * IE + ac4 * 4;
            int n = n0 + arow;
            bptr = Wa0 + ((size_t)e * H + n) * IE + ac4 * 4;
        } else {
            aptr = g_shmid + (size_t)(m0 + arow) * ISZ + ac4 * 4;
            int n = n0 + arow;
            bptr = Wa1 + (size_t)n * ISZ + ac4 * 4;
        }
    }

    float acc[2][4][4];
#pragma unroll
    for (int i = 0; i < 2; i++)
#pragma unroll
        for (int j = 0; j < 4; j++)
#pragma unroll
            for (int k = 0; k < 4; k++) acc[i][j][k] = 0.f;

    const int wid = tid >> 5, lane = tid & 31;
    const int wr = wid >> 2, wc = wid & 3;   // 4x4 warp grid, warp tile 32x32
    const int gq = lane >> 2, tg = lane & 3;

    const float4 z4 = make_float4(0.f, 0.f, 0.f, 0.f);

    // ---- stage 0 ----
    {
        float4 av = aptr ? *reinterpret_cast<const float4*>(aptr) : z4;
        float4 bv = *reinterpret_cast<const float4*>(bptr);
        *reinterpret_cast<uint2*>(&As[0][sdst]) =
            make_uint2(h2pack(av.x, av.y), h2pack(av.z, av.w));
        *reinterpret_cast<uint2*>(&Bs[0][sdst]) =
            make_uint2(h2pack(bv.x, bv.y), h2pack(bv.z, bv.w));
    }
    if (aptr) aptr += BK;
    bptr += BK;
    __syncthreads();

#pragma unroll 1
    for (int kt = 0; kt < ksteps; ++kt) {
        int cur = kt & 1;
        bool pf = (kt + 1) < ksteps;
        float4 av, bv;
        if (pf) {
            av = aptr ? *reinterpret_cast<const float4*>(aptr) : z4;
            bv = *reinterpret_cast<const float4*>(bptr);
            if (aptr) aptr += BK;
            bptr += BK;
        }

        const unsigned* Ab = As[cur];
        const unsigned* Bb = Bs[cur];
        unsigned af[2][4], bf[4][2];
#pragma unroll
        for (int mi = 0; mi < 2; mi++) {
            int r = wr * 32 + mi * 16 + gq;
            const unsigned* p = Ab + r * PW + tg;
            af[mi][0] = p[0];
            af[mi][1] = p[8 * PW];
            af[mi][2] = p[4];
            af[mi][3] = p[8 * PW + 4];
        }
#pragma unroll
        for (int ni = 0; ni < 4; ni++) {
            int nn = wc * 32 + ni * 8 + gq;
            const unsigned* p = Bb + nn * PW + tg;
            bf[ni][0] = p[0];
            bf[ni][1] = p[4];
        }
#pragma unroll
        for (int mi = 0; mi < 2; mi++)
#pragma unroll
            for (int ni = 0; ni < 4; ni++)
                mma16(acc[mi][ni], af[mi], bf[ni][0], bf[ni][1]);

        if (pf) {
            *reinterpret_cast<uint2*>(&As[cur ^ 1][sdst]) =
                make_uint2(h2pack(av.x, av.y), h2pack(av.z, av.w));
            *reinterpret_cast<uint2*>(&Bs[cur ^ 1][sdst]) =
                make_uint2(h2pack(bv.x, bv.y), h2pack(bv.z, bv.w));
        }
        __syncthreads();
    }

    // ---- epilogue ----
#pragma unroll
    for (int mi = 0; mi < 2; mi++) {
#pragma unroll
        for (int ni = 0; ni < 4; ni++) {
            int r = m0 + wr * 32 + mi * 16 + gq;
            int c = n0 + wc * 32 + ni * 8 + 2 * tg;
            float2 v0 = make_float2(acc[mi][ni][0], acc[mi][ni][1]);
            float2 v1 = make_float2(acc[mi][ni][2], acc[mi][ni][3]);
            if constexpr (PAIR == 0) {
                if (first) {
                    *reinterpret_cast<float2*>(&g_mid12[(size_t)r * 1024 + c])       = v0;
                    *reinterpret_cast<float2*>(&g_mid12[(size_t)(r + 8) * 1024 + c]) = v1;
                } else {
                    *reinterpret_cast<float2*>(&g_smid[(size_t)r * 4096 + c])       = v0;
                    *reinterpret_cast<float2*>(&g_smid[(size_t)(r + 8) * 4096 + c]) = v1;
                }
            } else {
                if (first) {
                    *reinterpret_cast<float2*>(&g_outp[(size_t)r * H + c])       = v0;
                    *reinterpret_cast<float2*>(&g_outp[(size_t)(r + 8) * H + c]) = v1;
                } else {
                    float ga0 = g_gate[r], ga1 = g_gate[r + 8];
                    v0.x *= ga0; v0.y *= ga0;
                    v1.x *= ga1; v1.y *= ga1;
                    *reinterpret_cast<float2*>(&Out[(size_t)r * H + c])       = v0;
                    *reinterpret_cast<float2*>(&Out[(size_t)(r + 8) * H + c]) = v1;
                }
            }
        }
    }
}

// ---------------- elementwise -------------------------------------------------
constexpr size_t N_SWI_E  = (size_t)MAXROWS * IE;       // 3,145,728
constexpr size_t N_SWI_SH = (size_t)T * ISZ;            // 4,194,304

__global__ void swiglu_all() {
    size_t idx = (size_t)blockIdx.x * blockDim.x + threadIdx.x;
    if (idx < N_SWI_E) {
        int row = (int)(idx / IE), i = (int)(idx % IE);
        float v = 0.f;
        if (g_rowtok[row] >= 0) {
            float gv = g_mid12[(size_t)row * 1024 + i];
            float uv = g_mid12[(size_t)row * 1024 + 512 + i];
            v = gv / (1.f + expf(-gv)) * uv * g_roww[row];
        }
        g_hmid[idx] = v;
    } else if (idx < N_SWI_E + N_SWI_SH) {
        size_t j = idx - N_SWI_E;
        int t = (int)(j / ISZ), i = (int)(j % ISZ);
        float gv = g_smid[(size_t)t * 2 * ISZ + i];
        float uv = g_smid[(size_t)t * 2 * ISZ + ISZ + i];
        g_shmid[j] = gv / (1.f + expf(-gv)) * uv;
    }
}

__global__ void final_add(float* __restrict__ out) {
    size_t idx = (size_t)blockIdx.x * blockDim.x + threadIdx.x;
    if (idx >= (size_t)T * H) return;
    int t = (int)(idx / H), h = (int)(idx % H);
    int p0 = g_pairslot[t * 2], p1 = g_pairslot[t * 2 + 1];
    out[idx] += g_outp[(size_t)p0 * H + h] + g_outp[(size_t)p1 * H + h];
}

// ---------------- launch ------------------------------------------------------
extern "C" void kernel_launch(void* const* d_in, const int* in_sizes, int n_in,
                              void* d_out, int out_size) {
    (void)in_sizes; (void)n_in; (void)out_size;
    const float* X   = (const float*)d_in[0];
    const float* GW  = (const float*)d_in[1];
    const float* W1  = (const float*)d_in[2];
    const float* W2  = (const float*)d_in[3];
    const float* W3  = (const float*)d_in[4];
    const float* WSG = (const float*)d_in[5];
    const float* WSU = (const float*)d_in[6];
    const float* WSD = (const float*)d_in[7];
    const float* SGW = (const float*)d_in[8];
    float* out = (float*)d_out;

    zero_init<<<(MAXROWS + 255) / 256, 256>>>();
    router_k<<<T / 4, 128>>>(X, GW, SGW);
    offsets_k<<<1, 32>>>();
    scatter_k<<<(T + 255) / 256, 256>>>();

    // PAIR 0: expert gate/up (384 blocks) + shared gate/up (512 blocks)
    gemm_k<0><<<896, THREADS>>>(X, W1, W3, WSG, WSU, nullptr);
    swiglu_all<<<(unsigned)((N_SWI_E + N_SWI_SH + 255) / 256), 256>>>();
    // PAIR 1: expert down (768 blocks) + shared down (256 blocks)
    gemm_k<1><<<1024, THREADS>>>(nullptr, W2, nullptr, WSD, nullptr, out);
    final_add<<<(T * H) / 256, 256>>>(out);
}

// round 16
// speedup vs baseline: 1.2898x; 1.2898x over previous
#include <cuda_runtime.h>
#include <cuda_fp16.h>
#include <cstdint>

#define DINLINE __device__ __forceinline__

constexpr int T   = 2048;   // tokens
constexpr int H   = 2048;   // hidden
constexpr int NE  = 16;     // experts
constexpr int IE  = 512;    // expert intermediate
constexpr int ISZ = 2048;   // shared intermediate
constexpr int MAXROWS  = 6144;  // 4096 pairs + 16*128 tile padding
constexpr int MAXTILES = 48;

constexpr int BM = 128, BN = 128, BK = 16;
constexpr int PW = 10;      // padded stride in half2 words (8 data + 2 pad)

// ---------------- scratch (device globals; no allocation allowed) ------------
__device__ int   g_counts[NE];
__device__ int   g_off[NE];
__device__ int   g_cursor[NE];
__device__ int   g_tile_expert[MAXTILES];
__device__ int   g_rowtok[MAXROWS];
__device__ float g_roww[MAXROWS];
__device__ int   g_sel[T * 2];
__device__ float g_wk[T * 2];
__device__ int   g_pairslot[T * 2];
__device__ float g_gate[T];
__device__ float g_mid12[(size_t)MAXROWS * 1024];   // expert gate|up raw
__device__ float g_hmid [(size_t)MAXROWS * IE];     // expert swiglu * weight
__device__ float g_outp [(size_t)MAXROWS * H];      // expert partial outputs
__device__ float g_smid [(size_t)T * 2 * ISZ];      // shared gate|up raw
__device__ float g_shmid[(size_t)T * ISZ];          // shared swiglu

// ---------------- small kernels ---------------------------------------------
__global__ void zero_init() {
    int i = blockIdx.x * blockDim.x + threadIdx.x;
    if (i < MAXROWS) { g_rowtok[i] = -1; g_roww[i] = 0.f; }
    if (i < NE) g_counts[i] = 0;
}

// One warp per token: 16 router logits + 1 shared-gate logit.
__global__ void router_k(const float* __restrict__ X,
                         const float* __restrict__ GW,
                         const float* __restrict__ SGW) {
    __shared__ float Ws[17][128];
    int lane = threadIdx.x & 31, warp = threadIdx.x >> 5;
    int t = blockIdx.x * 4 + warp;

    float acc[17];
#pragma unroll
    for (int e = 0; e < 17; e++) acc[e] = 0.f;

    for (int k0 = 0; k0 < H; k0 += 128) {
        __syncthreads();
        for (int j = threadIdx.x; j < 17 * 128; j += 128) {
            int e = j >> 7, kk = j & 127;
            Ws[e][kk] = (e < 16) ? GW[e * H + k0 + kk] : SGW[k0 + kk];
        }
        __syncthreads();
        float xv[4];
#pragma unroll
        for (int i = 0; i < 4; i++) xv[i] = X[(size_t)t * H + k0 + i * 32 + lane];
#pragma unroll
        for (int e = 0; e < 17; e++) {
#pragma unroll
            for (int i = 0; i < 4; i++) acc[e] += xv[i] * Ws[e][i * 32 + lane];
        }
    }
#pragma unroll
    for (int e = 0; e < 17; e++) {
        float v = acc[e];
#pragma unroll
        for (int o = 16; o > 0; o >>= 1) v += __shfl_xor_sync(0xffffffffu, v, o);
        acc[e] = v;
    }
    if (lane == 0) {
        int i1 = 0;
        for (int e = 1; e < 16; e++) if (acc[e] > acc[i1]) i1 = e;
        int i2 = (i1 == 0) ? 1 : 0;
        for (int e = 0; e < 16; e++) if (e != i1 && acc[e] > acc[i2]) i2 = e;
        float m  = acc[i1];
        float e1 = expf(acc[i1] - m), e2 = expf(acc[i2] - m);
        float s  = e1 + e2;
        g_sel[t * 2] = i1;  g_sel[t * 2 + 1] = i2;
        g_wk [t * 2] = e1 / s;  g_wk [t * 2 + 1] = e2 / s;
        atomicAdd(&g_counts[i1], 1);
        atomicAdd(&g_counts[i2], 1);
        g_gate[t] = 1.f / (1.f + expf(-acc[16]));
    }
}

__global__ void offsets_k() {
    if (threadIdx.x == 0 && blockIdx.x == 0) {
        int off = 0, tile = 0;
        for (int e = 0; e < NE; e++) {
            g_off[e] = off;
            g_cursor[e] = 0;
            int nt = (g_counts[e] + BM - 1) / BM;
            for (int j = 0; j < nt; j++) g_tile_expert[tile++] = e;
            off += nt * BM;
        }
        for (; tile < MAXTILES; tile++) g_tile_expert[tile] = -1;
    }
}

__global__ void scatter_k() {
    int t = blockIdx.x * blockDim.x + threadIdx.x;
    if (t >= T) return;
#pragma unroll
    for (int k = 0; k < 2; k++) {
        int e   = g_sel[t * 2 + k];
        int pos = atomicAdd(&g_cursor[e], 1);
        int row = g_off[e] + pos;
        g_rowtok[row] = t;
        g_roww[row]   = g_wk[t * 2 + k];
        g_pairslot[t * 2 + k] = row;
    }
}

// ---------------- fp16 MMA GEMM ----------------------------------------------
DINLINE unsigned h2pack(float x, float y) {
    __half2 h = __floats2half2_rn(x, y);
    return *reinterpret_cast<unsigned*>(&h);
}
DINLINE void mma16(float* c, const unsigned* a, unsigned b0, unsigned b1) {
    asm volatile(
        "mma.sync.aligned.m16n8k16.row.col.f32.f16.f16.f32 "
        "{%0,%1,%2,%3}, {%4,%5,%6,%7}, {%8,%9}, {%0,%1,%2,%3};"
        : "+f"(c[0]), "+f"(c[1]), "+f"(c[2]), "+f"(c[3])
        : "r"(a[0]), "r"(a[1]), "r"(a[2]), "r"(a[3]), "r"(b0), "r"(b1));
}

// Load 8 floats and pack immediately to 4 half2 words (low register footprint).
DINLINE void ldpack(const float* p, unsigned* q) {
    float4 v0 = *reinterpret_cast<const float4*>(p);
    float4 v1 = *reinterpret_cast<const float4*>(p + 4);
    q[0] = h2pack(v0.x, v0.y);
    q[1] = h2pack(v0.z, v0.w);
    q[2] = h2pack(v1.x, v1.y);
    q[3] = h2pack(v1.z, v1.w);
}

// 256 threads, 8 warps (2x4 warp grid), warp tile 64x32, occupancy 2.
// Smem stores are uint2 (8B) — sdst is always even, so 8B alignment holds
// (uint4 would need sdst % 4 == 0, which PW=10 violates for odd rows).
// PAIR 0: blocks [0, 384)   -> expert gate/up, C[row,1024], K=2048
//         blocks [384, 896) -> shared gate/up, C[t,4096],   K=2048 (Wa1=ws_gate, Wb1=ws_up)
// PAIR 1: blocks [0, 768)   -> expert down,    C[row,2048], K=512
//         blocks [768,1024) -> shared down,    out,         K=2048 (Wa1=ws_down)
template <int PAIR>
__global__ void __launch_bounds__(256, 2)
gemm_k(const float* __restrict__ X,
       const float* __restrict__ Wa0, const float* __restrict__ Wb0,
       const float* __restrict__ Wa1, const float* __restrict__ Wb1,
       float* __restrict__ Out) {
    __shared__ __align__(16) unsigned As[2][BM * PW];
    __shared__ __align__(16) unsigned Bs[2][BN * PW];

    const int bid = blockIdx.x;
    const int tid = threadIdx.x;

    bool first;
    int bx, by;
    int ksteps;
    if constexpr (PAIR == 0) {
        first = bid < 384;
        if (first) { bx = bid & 7;  by = bid >> 3; }
        else       { int r = bid - 384; bx = r & 31; by = r >> 5; }
        ksteps = 128;
    } else {
        first = bid < 768;
        if (first) { bx = bid & 15; by = bid >> 4; ksteps = 32; }
        else       { int r = bid - 768; bx = r & 15; by = r >> 4; ksteps = 128; }
    }

    int e = 0;
    if (first) {
        e = g_tile_expert[by];
        if (e < 0) return;
    }
    const int m0 = by * BM, n0 = bx * BN;
    const int arow = tid >> 1, acol = (tid & 1) * 8;   // 8 floats per thread

    const float* aptr = nullptr;
    const float* bptr;
    if constexpr (PAIR == 0) {
        if (first) {
            int tok = g_rowtok[m0 + arow];
            if (tok >= 0) aptr = X + (size_t)tok * H + acol;
            int n = n0 + arow;
            bptr = ((n < IE) ? (Wa0 + ((size_t)e * IE + n) * H)
                             : (Wb0 + ((size_t)e * IE + (n - IE)) * H)) + acol;
        } else {
            aptr = X + (size_t)(m0 + arow) * H + acol;
            int n = n0 + arow;
            bptr = ((n < ISZ) ? (Wa1 + (size_t)n * H)
                              : (Wb1 + (size_t)(n - ISZ) * H)) + acol;
        }
    } else {
        if (first) {
            aptr = g_hmid + (size_t)(m0 + arow) * IE + acol;
            int n = n0 + arow;
            bptr = Wa0 + ((size_t)e * H + n) * IE + acol;
        } else {
            aptr = g_shmid + (size_t)(m0 + arow) * ISZ + acol;
            int n = n0 + arow;
            bptr = Wa1 + (size_t)n * ISZ + acol;
        }
    }

    float acc[4][4][4];
#pragma unroll
    for (int i = 0; i < 4; i++)
#pragma unroll
        for (int j = 0; j < 4; j++)
#pragma unroll
            for (int k = 0; k < 4; k++) acc[i][j][k] = 0.f;

    const int wid = tid >> 5, lane = tid & 31;
    const int wr = wid >> 2, wc = wid & 3;   // 2x4 warp grid, warp tile 64x32
    const int gq = lane >> 2, tg = lane & 3;

    const int sdst = arow * PW + acol / 2;   // always even -> 8B aligned

    // ---- stage 0 ----
    {
        unsigned aw[4] = {0u, 0u, 0u, 0u}, bw[4];
        if (aptr) ldpack(aptr, aw);
        ldpack(bptr, bw);
        *reinterpret_cast<uint2*>(&As[0][sdst])     = make_uint2(aw[0], aw[1]);
        *reinterpret_cast<uint2*>(&As[0][sdst + 2]) = make_uint2(aw[2], aw[3]);
        *reinterpret_cast<uint2*>(&Bs[0][sdst])     = make_uint2(bw[0], bw[1]);
        *reinterpret_cast<uint2*>(&Bs[0][sdst + 2]) = make_uint2(bw[2], bw[3]);
    }
    if (aptr) aptr += BK;
    bptr += BK;
    __syncthreads();

#pragma unroll 1
    for (int kt = 0; kt < ksteps; ++kt) {
        int cur = kt & 1;
        bool pf = (kt + 1) < ksteps;
        unsigned aw[4] = {0u, 0u, 0u, 0u}, bw[4];
        if (pf) {
            if (aptr) { ldpack(aptr, aw); aptr += BK; }
            ldpack(bptr, bw);
            bptr += BK;
        }

        const unsigned* Ab = As[cur];
        const unsigned* Bb = Bs[cur];
        unsigned af[4][4], bf[4][2];
#pragma unroll
        for (int mi = 0; mi < 4; mi++) {
            int r = wr * 64 + mi * 16 + gq;
            const unsigned* p = Ab + r * PW + tg;
            af[mi][0] = p[0];
            af[mi][1] = p[8 * PW];
            af[mi][2] = p[4];
            af[mi][3] = p[8 * PW + 4];
        }
#pragma unroll
        for (int ni = 0; ni < 4; ni++) {
            int nn = wc * 32 + ni * 8 + gq;
            const unsigned* p = Bb + nn * PW + tg;
            bf[ni][0] = p[0];
            bf[ni][1] = p[4];
        }
#pragma unroll
        for (int mi = 0; mi < 4; mi++)
#pragma unroll
            for (int ni = 0; ni < 4; ni++)
                mma16(acc[mi][ni], af[mi], bf[ni][0], bf[ni][1]);

        if (pf) {
            unsigned* da = &As[cur ^ 1][sdst];
            unsigned* db = &Bs[cur ^ 1][sdst];
            *reinterpret_cast<uint2*>(da)     = make_uint2(aw[0], aw[1]);
            *reinterpret_cast<uint2*>(da + 2) = make_uint2(aw[2], aw[3]);
            *reinterpret_cast<uint2*>(db)     = make_uint2(bw[0], bw[1]);
            *reinterpret_cast<uint2*>(db + 2) = make_uint2(bw[2], bw[3]);
        }
        __syncthreads();
    }

    // ---- epilogue ----
#pragma unroll
    for (int mi = 0; mi < 4; mi++) {
#pragma unroll
        for (int ni = 0; ni < 4; ni++) {
            int r = m0 + wr * 64 + mi * 16 + gq;
            int c = n0 + wc * 32 + ni * 8 + 2 * tg;
            float2 v0 = make_float2(acc[mi][ni][0], acc[mi][ni][1]);
            float2 v1 = make_float2(acc[mi][ni][2], acc[mi][ni][3]);
            if constexpr (PAIR == 0) {
                if (first) {
                    *reinterpret_cast<float2*>(&g_mid12[(size_t)r * 1024 + c])       = v0;
                    *reinterpret_cast<float2*>(&g_mid12[(size_t)(r + 8) * 1024 + c]) = v1;
                } else {
                    *reinterpret_cast<float2*>(&g_smid[(size_t)r * 4096 + c])       = v0;
                    *reinterpret_cast<float2*>(&g_smid[(size_t)(r + 8) * 4096 + c]) = v1;
                }
            } else {
                if (first) {
                    *reinterpret_cast<float2*>(&g_outp[(size_t)r * H + c])       = v0;
                    *reinterpret_cast<float2*>(&g_outp[(size_t)(r + 8) * H + c]) = v1;
                } else {
                    float ga0 = g_gate[r], ga1 = g_gate[r + 8];
                    v0.x *= ga0; v0.y *= ga0;
                    v1.x *= ga1; v1.y *= ga1;
                    *reinterpret_cast<float2*>(&Out[(size_t)r * H + c])       = v0;
                    *reinterpret_cast<float2*>(&Out[(size_t)(r + 8) * H + c]) = v1;
                }
            }
        }
    }
}

// ---------------- elementwise -------------------------------------------------
constexpr size_t N_SWI_E  = (size_t)MAXROWS * IE;       // 3,145,728
constexpr size_t N_SWI_SH = (size_t)T * ISZ;            // 4,194,304

__global__ void swiglu_all() {
    size_t idx = (size_t)blockIdx.x * blockDim.x + threadIdx.x;
    if (idx < N_SWI_E) {
        int row = (int)(idx / IE), i = (int)(idx % IE);
        float v = 0.f;
        if (g_rowtok[row] >= 0) {
            float gv = g_mid12[(size_t)row * 1024 + i];
            float uv = g_mid12[(size_t)row * 1024 + 512 + i];
            v = gv / (1.f + expf(-gv)) * uv * g_roww[row];
        }
        g_hmid[idx] = v;
    } else if (idx < N_SWI_E + N_SWI_SH) {
        size_t j = idx - N_SWI_E;
        int t = (int)(j / ISZ), i = (int)(j % ISZ);
        float gv = g_smid[(size_t)t * 2 * ISZ + i];
        float uv = g_smid[(size_t)t * 2 * ISZ + ISZ + i];
        g_shmid[j] = gv / (1.f + expf(-gv)) * uv;
    }
}

__global__ void final_add(float* __restrict__ out) {
    size_t idx = (size_t)blockIdx.x * blockDim.x + threadIdx.x;
    if (idx >= (size_t)T * H) return;
    int t = (int)(idx / H), h = (int)(idx % H);
    int p0 = g_pairslot[t * 2], p1 = g_pairslot[t * 2 + 1];
    out[idx] += g_outp[(size_t)p0 * H + h] + g_outp[(size_t)p1 * H + h];
}

// ---------------- launch ------------------------------------------------------
extern "C" void kernel_launch(void* const* d_in, const int* in_sizes, int n_in,
                              void* d_out, int out_size) {
    (void)in_sizes; (void)n_in; (void)out_size;
    const float* X   = (const float*)d_in[0];
    const float* GW  = (const float*)d_in[1];
    const float* W1  = (const float*)d_in[2];
    const float* W2  = (const float*)d_in[3];
    const float* W3  = (const float*)d_in[4];
    const float* WSG = (const float*)d_in[5];
    const float* WSU = (const float*)d_in[6];
    const float* WSD = (const float*)d_in[7];
    const float* SGW = (const float*)d_in[8];
    float* out = (float*)d_out;

    zero_init<<<(MAXROWS + 255) / 256, 256>>>();
    router_k<<<T / 4, 128>>>(X, GW, SGW);
    offsets_k<<<1, 32>>>();
    scatter_k<<<(T + 255) / 256, 256>>>();

    // PAIR 0: expert gate/up (384 blocks) + shared gate/up (512 blocks)
    gemm_k<0><<<896, 256>>>(X, W1, W3, WSG, WSU, nullptr);
    swiglu_all<<<(unsigned)((N_SWI_E + N_SWI_SH + 255) / 256), 256>>>();
    // PAIR 1: expert down (768 blocks) + shared down (256 blocks)
    gemm_k<1><<<1024, 256>>>(nullptr, W2, nullptr, WSD, nullptr, out);
    final_add<<<(T * H) / 256, 256>>>(out);
}

// round 17
// speedup vs baseline: 1.4579x; 1.1304x over previous
#include <cuda_runtime.h>
#include <cuda_fp16.h>
#include <cstdint>

#define DINLINE __device__ __forceinline__

constexpr int T   = 2048;   // tokens
constexpr int H   = 2048;   // hidden
constexpr int NE  = 16;     // experts
constexpr int IE  = 512;    // expert intermediate
constexpr int ISZ = 2048;   // shared intermediate
constexpr int MAXROWS  = 6144;  // 4096 pairs + 16*128 tile padding
constexpr int MAXTILES = 48;

constexpr int BM = 128, BN = 128, BK = 16;
constexpr int PW = 12;      // padded stride in half2 words (8 data + 4 pad)
                            // gq*12+tg covers all 32 banks exactly once ->
                            // conflict-free fragment LDS (PW=10 was 2-way).

// ---------------- scratch (device globals; no allocation allowed) ------------
__device__ int   g_counts[NE];
__device__ int   g_off[NE];
__device__ int   g_cursor[NE];
__device__ int   g_tile_expert[MAXTILES];
__device__ int   g_rowtok[MAXROWS];
__device__ float g_roww[MAXROWS];
__device__ int   g_sel[T * 2];
__device__ float g_wk[T * 2];
__device__ int   g_pairslot[T * 2];
__device__ float g_gate[T];
__device__ float g_mid12[(size_t)MAXROWS * 1024];   // expert gate|up raw
__device__ float g_hmid [(size_t)MAXROWS * IE];     // expert swiglu * weight
__device__ float g_outp [(size_t)MAXROWS * H];      // expert partial outputs
__device__ float g_smid [(size_t)T * 2 * ISZ];      // shared gate|up raw
__device__ float g_shmid[(size_t)T * ISZ];          // shared swiglu

// ---------------- small kernels ---------------------------------------------
__global__ void zero_init() {
    int i = blockIdx.x * blockDim.x + threadIdx.x;
    if (i < MAXROWS) { g_rowtok[i] = -1; g_roww[i] = 0.f; }
    if (i < NE) g_counts[i] = 0;
}

// One warp per token: 16 router logits + 1 shared-gate logit.
__global__ void router_k(const float* __restrict__ X,
                         const float* __restrict__ GW,
                         const float* __restrict__ SGW) {
    __shared__ float Ws[17][128];
    int lane = threadIdx.x & 31, warp = threadIdx.x >> 5;
    int t = blockIdx.x * 4 + warp;

    float acc[17];
#pragma unroll
    for (int e = 0; e < 17; e++) acc[e] = 0.f;

    for (int k0 = 0; k0 < H; k0 += 128) {
        __syncthreads();
        for (int j = threadIdx.x; j < 17 * 128; j += 128) {
            int e = j >> 7, kk = j & 127;
            Ws[e][kk] = (e < 16) ? GW[e * H + k0 + kk] : SGW[k0 + kk];
        }
        __syncthreads();
        float xv[4];
#pragma unroll
        for (int i = 0; i < 4; i++) xv[i] = X[(size_t)t * H + k0 + i * 32 + lane];
#pragma unroll
        for (int e = 0; e < 17; e++) {
#pragma unroll
            for (int i = 0; i < 4; i++) acc[e] += xv[i] * Ws[e][i * 32 + lane];
        }
    }
#pragma unroll
    for (int e = 0; e < 17; e++) {
        float v = acc[e];
#pragma unroll
        for (int o = 16; o > 0; o >>= 1) v += __shfl_xor_sync(0xffffffffu, v, o);
        acc[e] = v;
    }
    if (lane == 0) {
        int i1 = 0;
        for (int e = 1; e < 16; e++) if (acc[e] > acc[i1]) i1 = e;
        int i2 = (i1 == 0) ? 1 : 0;
        for (int e = 0; e < 16; e++) if (e != i1 && acc[e] > acc[i2]) i2 = e;
        float m  = acc[i1];
        float e1 = expf(acc[i1] - m), e2 = expf(acc[i2] - m);
        float s  = e1 + e2;
        g_sel[t * 2] = i1;  g_sel[t * 2 + 1] = i2;
        g_wk [t * 2] = e1 / s;  g_wk [t * 2 + 1] = e2 / s;
        atomicAdd(&g_counts[i1], 1);
        atomicAdd(&g_counts[i2], 1);
        g_gate[t] = 1.f / (1.f + expf(-acc[16]));
    }
}

__global__ void offsets_k() {
    if (threadIdx.x == 0 && blockIdx.x == 0) {
        int off = 0, tile = 0;
        for (int e = 0; e < NE; e++) {
            g_off[e] = off;
            g_cursor[e] = 0;
            int nt = (g_counts[e] + BM - 1) / BM;
            for (int j = 0; j < nt; j++) g_tile_expert[tile++] = e;
            off += nt * BM;
        }
        for (; tile < MAXTILES; tile++) g_tile_expert[tile] = -1;
    }
}

__global__ void scatter_k() {
    int t = blockIdx.x * blockDim.x + threadIdx.x;
    if (t >= T) return;
#pragma unroll
    for (int k = 0; k < 2; k++) {
        int e   = g_sel[t * 2 + k];
        int pos = atomicAdd(&g_cursor[e], 1);
        int row = g_off[e] + pos;
        g_rowtok[row] = t;
        g_roww[row]   = g_wk[t * 2 + k];
        g_pairslot[t * 2 + k] = row;
    }
}

// ---------------- fp16 MMA GEMM ----------------------------------------------
DINLINE unsigned h2pack(float x, float y) {
    __half2 h = __floats2half2_rn(x, y);
    return *reinterpret_cast<unsigned*>(&h);
}
DINLINE void mma16(float* c, const unsigned* a, unsigned b0, unsigned b1) {
    asm volatile(
        "mma.sync.aligned.m16n8k16.row.col.f32.f16.f16.f32 "
        "{%0,%1,%2,%3}, {%4,%5,%6,%7}, {%8,%9}, {%0,%1,%2,%3};"
        : "+f"(c[0]), "+f"(c[1]), "+f"(c[2]), "+f"(c[3])
        : "r"(a[0]), "r"(a[1]), "r"(a[2]), "r"(a[3]), "r"(b0), "r"(b1));
}

// Load 8 floats and pack immediately to 4 half2 words (low register footprint).
DINLINE void ldpack(const float* p, unsigned* q) {
    float4 v0 = *reinterpret_cast<const float4*>(p);
    float4 v1 = *reinterpret_cast<const float4*>(p + 4);
    q[0] = h2pack(v0.x, v0.y);
    q[1] = h2pack(v0.z, v0.w);
    q[2] = h2pack(v1.x, v1.y);
    q[3] = h2pack(v1.z, v1.w);
}

// 256 threads, 8 warps (2x4 warp grid), warp tile 64x32, occupancy 2.
// Smem stores are uint2 (8B) — sdst is always even, so 8B alignment holds.
// PAIR 0: blocks [0, 384)   -> expert gate/up, C[row,1024], K=2048
//         blocks [384, 896) -> shared gate/up, C[t,4096],   K=2048 (Wa1=ws_gate, Wb1=ws_up)
// PAIR 1: blocks [0, 768)   -> expert down,    C[row,2048], K=512
//         blocks [768,1024) -> shared down,    out,         K=2048 (Wa1=ws_down)
template <int PAIR>
__global__ void __launch_bounds__(256, 2)
gemm_k(const float* __restrict__ X,
       const float* __restrict__ Wa0, const float* __restrict__ Wb0,
       const float* __restrict__ Wa1, const float* __restrict__ Wb1,
       float* __restrict__ Out) {
    __shared__ __align__(16) unsigned As[2][BM * PW];
    __shared__ __align__(16) unsigned Bs[2][BN * PW];

    const int bid = blockIdx.x;
    const int tid = threadIdx.x;

    bool first;
    int bx, by;
    int ksteps;
    if constexpr (PAIR == 0) {
        first = bid < 384;
        if (first) { bx = bid & 7;  by = bid >> 3; }
        else       { int r = bid - 384; bx = r & 31; by = r >> 5; }
        ksteps = 128;
    } else {
        first = bid < 768;
        if (first) { bx = bid & 15; by = bid >> 4; ksteps = 32; }
        else       { int r = bid - 768; bx = r & 15; by = r >> 4; ksteps = 128; }
    }

    int e = 0;
    if (first) {
        e = g_tile_expert[by];
        if (e < 0) return;
    }
    const int m0 = by * BM, n0 = bx * BN;
    const int arow = tid >> 1, acol = (tid & 1) * 8;   // 8 floats per thread

    const float* aptr = nullptr;
    const float* bptr;
    if constexpr (PAIR == 0) {
        if (first) {
            int tok = g_rowtok[m0 + arow];
            if (tok >= 0) aptr = X + (size_t)tok * H + acol;
            int n = n0 + arow;
            bptr = ((n < IE) ? (Wa0 + ((size_t)e * IE + n) * H)
                             : (Wb0 + ((size_t)e * IE + (n - IE)) * H)) + acol;
        } else {
            aptr = X + (size_t)(m0 + arow) * H + acol;
            int n = n0 + arow;
            bptr = ((n < ISZ) ? (Wa1 + (size_t)n * H)
                              : (Wb1 + (size_t)(n - ISZ) * H)) + acol;
        }
    } else {
        if (first) {
            aptr = g_hmid + (size_t)(m0 + arow) * IE + acol;
            int n = n0 + arow;
            bptr = Wa0 + ((size_t)e * H + n) * IE + acol;
        } else {
            aptr = g_shmid + (size_t)(m0 + arow) * ISZ + acol;
            int n = n0 + arow;
            bptr = Wa1 + (size_t)n * ISZ + acol;
        }
    }

    float acc[4][4][4];
#pragma unroll
    for (int i = 0; i < 4; i++)
#pragma unroll
        for (int j = 0; j < 4; j++)
#pragma unroll
            for (int k = 0; k < 4; k++) acc[i][j][k] = 0.f;

    const int wid = tid >> 5, lane = tid & 31;
    const int wr = wid >> 2, wc = wid & 3;   // 2x4 warp grid, warp tile 64x32
    const int gq = lane >> 2, tg = lane & 3;

    const int sdst = arow * PW + acol / 2;   // always even -> 8B aligned

    // ---- stage 0 ----
    {
        unsigned aw[4] = {0u, 0u, 0u, 0u}, bw[4];
        if (aptr) ldpack(aptr, aw);
        ldpack(bptr, bw);
        *reinterpret_cast<uint2*>(&As[0][sdst])     = make_uint2(aw[0], aw[1]);
        *reinterpret_cast<uint2*>(&As[0][sdst + 2]) = make_uint2(aw[2], aw[3]);
        *reinterpret_cast<uint2*>(&Bs[0][sdst])     = make_uint2(bw[0], bw[1]);
        *reinterpret_cast<uint2*>(&Bs[0][sdst + 2]) = make_uint2(bw[2], bw[3]);
    }
    if (aptr) aptr += BK;
    bptr += BK;
    __syncthreads();

#pragma unroll 1
    for (int kt = 0; kt < ksteps; ++kt) {
        int cur = kt & 1;
        bool pf = (kt + 1) < ksteps;
        unsigned aw[4] = {0u, 0u, 0u, 0u}, bw[4];
        if (pf) {
            if (aptr) { ldpack(aptr, aw); aptr += BK; }
            ldpack(bptr, bw);
            bptr += BK;
        }

        const unsigned* Ab = As[cur];
        const unsigned* Bb = Bs[cur];
        unsigned af[4][4], bf[4][2];
#pragma unroll
        for (int mi = 0; mi < 4; mi++) {
            int r = wr * 64 + mi * 16 + gq;
            const unsigned* p = Ab + r * PW + tg;
            af[mi][0] = p[0];
            af[mi][1] = p[8 * PW];
            af[mi][2] = p[4];
            af[mi][3] = p[8 * PW + 4];
        }
#pragma unroll
        for (int ni = 0; ni < 4; ni++) {
            int nn = wc * 32 + ni * 8 + gq;
            const unsigned* p = Bb + nn * PW + tg;
            bf[ni][0] = p[0];
            bf[ni][1] = p[4];
        }
#pragma unroll
        for (int mi = 0; mi < 4; mi++)
#pragma unroll
            for (int ni = 0; ni < 4; ni++)
                mma16(acc[mi][ni], af[mi], bf[ni][0], bf[ni][1]);

        if (pf) {
            unsigned* da = &As[cur ^ 1][sdst];
            unsigned* db = &Bs[cur ^ 1][sdst];
            *reinterpret_cast<uint2*>(da)     = make_uint2(aw[0], aw[1]);
            *reinterpret_cast<uint2*>(da + 2) = make_uint2(aw[2], aw[3]);
            *reinterpret_cast<uint2*>(db)     = make_uint2(bw[0], bw[1]);
            *reinterpret_cast<uint2*>(db + 2) = make_uint2(bw[2], bw[3]);
        }
        __syncthreads();
    }

    // ---- epilogue ----
#pragma unroll
    for (int mi = 0; mi < 4; mi++) {
#pragma unroll
        for (int ni = 0; ni < 4; ni++) {
            int r = m0 + wr * 64 + mi * 16 + gq;
            int c = n0 + wc * 32 + ni * 8 + 2 * tg;
            float2 v0 = make_float2(acc[mi][ni][0], acc[mi][ni][1]);
            float2 v1 = make_float2(acc[mi][ni][2], acc[mi][ni][3]);
            if constexpr (PAIR == 0) {
                if (first) {
                    *reinterpret_cast<float2*>(&g_mid12[(size_t)r * 1024 + c])       = v0;
                    *reinterpret_cast<float2*>(&g_mid12[(size_t)(r + 8) * 1024 + c]) = v1;
                } else {
                    *reinterpret_cast<float2*>(&g_smid[(size_t)r * 4096 + c])       = v0;
                    *reinterpret_cast<float2*>(&g_smid[(size_t)(r + 8) * 4096 + c]) = v1;
                }
            } else {
                if (first) {
                    *reinterpret_cast<float2*>(&g_outp[(size_t)r * H + c])       = v0;
                    *reinterpret_cast<float2*>(&g_outp[(size_t)(r + 8) * H + c]) = v1;
                } else {
                    float ga0 = g_gate[r], ga1 = g_gate[r + 8];
                    v0.x *= ga0; v0.y *= ga0;
                    v1.x *= ga1; v1.y *= ga1;
                    *reinterpret_cast<float2*>(&Out[(size_t)r * H + c])       = v0;
                    *reinterpret_cast<float2*>(&Out[(size_t)(r + 8) * H + c]) = v1;
                }
            }
        }
    }
}

// ---------------- elementwise -------------------------------------------------
constexpr size_t N_SWI_E  = (size_t)MAXROWS * IE;       // 3,145,728
constexpr size_t N_SWI_SH = (size_t)T * ISZ;            // 4,194,304

__global__ void swiglu_all() {
    size_t idx = (size_t)blockIdx.x * blockDim.x + threadIdx.x;
    if (idx < N_SWI_E) {
        int row = (int)(idx / IE), i = (int)(idx % IE);
        float v = 0.f;
        if (g_rowtok[row] >= 0) {
            float gv = g_mid12[(size_t)row * 1024 + i];
            float uv = g_mid12[(size_t)row * 1024 + 512 + i];
            v = gv / (1.f + expf(-gv)) * uv * g_roww[row];
        }
        g_hmid[idx] = v;
    } else if (idx < N_SWI_E + N_SWI_SH) {
        size_t j = idx - N_SWI_E;
        int t = (int)(j / ISZ), i = (int)(j % ISZ);
        float gv = g_smid[(size_t)t * 2 * ISZ + i];
        float uv = g_smid[(size_t)t * 2 * ISZ + ISZ + i];
        g_shmid[j] = gv / (1.f + expf(-gv)) * uv;
    }
}

__global__ void final_add(float* __restrict__ out) {
    size_t idx = (size_t)blockIdx.x * blockDim.x + threadIdx.x;
    if (idx >= (size_t)T * H) return;
    int t = (int)(idx / H), h = (int)(idx % H);
    int p0 = g_pairslot[t * 2], p1 = g_pairslot[t * 2 + 1];
    out[idx] += g_outp[(size_t)p0 * H + h] + g_outp[(size_t)p1 * H + h];
}

// ---------------- launch ------------------------------------------------------
extern "C" void kernel_launch(void* const* d_in, const int* in_sizes, int n_in,
                              void* d_out, int out_size) {
    (void)in_sizes; (void)n_in; (void)out_size;
    const float* X   = (const float*)d_in[0];
    const float* GW  = (const float*)d_in[1];
    const float* W1  = (const float*)d_in[2];
    const float* W2  = (const float*)d_in[3];
    const float* W3  = (const float*)d_in[4];
    const float* WSG = (const float*)d_in[5];
    const float* WSU = (const float*)d_in[6];
    const float* WSD = (const float*)d_in[7];
    const float* SGW = (const float*)d_in[8];
    float* out = (float*)d_out;

    zero_init<<<(MAXROWS + 255) / 256, 256>>>();
    router_k<<<T / 4, 128>>>(X, GW, SGW);
    offsets_k<<<1, 32>>>();
    scatter_k<<<(T + 255) / 256, 256>>>();

    // PAIR 0: expert gate/up (384 blocks) + shared gate/up (512 blocks)
    gemm_k<0><<<896, 256>>>(X, W1, W3, WSG, WSU, nullptr);
    swiglu_all<<<(unsigned)((N_SWI_E + N_SWI_SH + 255) / 256), 256>>>();
    // PAIR 1: expert down (768 blocks) + shared down (256 blocks)
    gemm_k<1><<<1024, 256>>>(nullptr, W2, nullptr, WSD, nullptr, out);
    final_add<<<(T * H) / 256, 256>>>(out);
}